// round 11
// baseline (speedup 1.0000x reference)
#include <cuda_runtime.h>
#include <cstdint>

// Problem constants
#define Bb 32
#define Cc 64
#define Lc 8192
#define Mm (Bb * Lc)            // 262144 columns
#define NBLK 444                // 148 SMs x 3 resident blocks = single balanced wave
#define NBLK_PAD 448            // padded partial count (slots 444..447 stay 0)
#define NT_G 2048               // gram tiles (128 cols each)
#define NT_A 2048               // apply tiles (128 cols each)
#define GPAD 132                // gram tile row stride (conflict-spreading pad)
#define EPSV 1e-5f

// ---------------- scratch (device globals; no allocation allowed) ----------------
// Zero-initialized at module load; slots [NBLK..NBLK_PAD) are never written and
// therefore always 0 -> deterministic padded reduction.
__device__ __align__(16) float g_gram_part[NBLK_PAD * 4096];
__device__ __align__(16) float g_sum_part[NBLK_PAD * 64];
__device__ __align__(16) float g_gram[4096];
__device__ __align__(16) float g_mean[64];
__device__ __align__(16) float g_wmT[4096];                // wmT[k][c] = wm[c][k]
__device__ __align__(16) float g_bias[64];                 // wm @ mean

// ---------------- f32x2 helpers (FFMA2: 2x fp32 FMA throughput) ----------------
__device__ __forceinline__ unsigned long long dup2(float v) {
    unsigned long long r;
    asm("mov.b64 %0, {%1, %1};" : "=l"(r) : "f"(v));
    return r;
}
__device__ __forceinline__ void fma2(unsigned long long& d, unsigned long long a,
                                     unsigned long long b) {
    asm("fma.rn.f32x2 %0, %1, %2, %0;" : "+l"(d) : "l"(a), "l"(b));
}
__device__ __forceinline__ float2 unpk(unsigned long long v) {
    float2 r;
    asm("mov.b64 {%0, %1}, %2;" : "=f"(r.x), "=f"(r.y) : "l"(v));
    return r;
}
__device__ __forceinline__ uint32_t smem_u32(const void* p) {
    uint32_t a;
    asm("{ .reg .u64 t; cvta.to.shared.u64 t, %1; cvt.u32.u64 %0, t; }"
        : "=r"(a) : "l"(p));
    return a;
}
__device__ __forceinline__ void cpasync16(uint32_t dst, const float* src) {
    asm volatile("cp.async.cg.shared.global [%0], [%1], 16;" :: "r"(dst), "l"(src));
}
#define CP_COMMIT() asm volatile("cp.async.commit_group;" ::: "memory")
#define CP_WAIT(n)  asm volatile("cp.async.wait_group %0;" :: "n"(n) : "memory")

// ================= Kernel 1: per-block partial Gram + channel sums =================
// Grid 444 @ occ 3 (TRUE 3 resident blocks/SM: inter-block overlap hides loads,
// syncs, and epilogues). SINGLE-buffered 64c x 128l tile (33.8 KB). PAIR-OVER-L
// f32x2 accumulators (horizontal-summed once at the end): both operands are direct
// vector LDS from the natural s[c][l] layout -> no transpose, no dup2, no split-k.
#define GRAM_SMEM (64 * GPAD * (int)sizeof(float))

__global__ __launch_bounds__(256, 3) void gram_kernel(const float* __restrict__ X) {
    extern __shared__ float gsm[];                      // [64][GPAD]
    const int tid = threadIdx.x;
    const int bid = blockIdx.x;
    const int ts = (bid * NT_G) / NBLK;
    const int te = ((bid + 1) * NT_G) / NBLK;

    const int ty = tid >> 4, tx = tid & 15;
    const int r = ty * 4;
    const uint32_t sbase = smem_u32(gsm);

    unsigned long long acc[4][4];
    #pragma unroll
    for (int i = 0; i < 4; i++) { acc[i][0] = acc[i][1] = acc[i][2] = acc[i][3] = 0ull; }
    float csum = 0.f;

    #pragma unroll 1
    for (int i = ts; i < te; i++) {
        {
            int bb = i >> 6, l0 = (i & 63) << 7;
            const float* Xb = X + (size_t)bb * (Cc * Lc) + l0;
            #pragma unroll
            for (int it = 0; it < 8; it++) {
                int p = it * 256 + tid, c = p >> 5, l4 = p & 31;
                cpasync16(sbase + (uint32_t)(c * GPAD + l4 * 4) * 4,
                          Xb + (size_t)c * Lc + l4 * 4);
            }
            CP_COMMIT();
            CP_WAIT(0);
        }
        __syncthreads();

        #pragma unroll 2
        for (int l4 = 0; l4 < 32; l4++) {
            const float* bp = gsm + l4 * 4;
            ulonglong2 a0 = *(const ulonglong2*)&bp[(r + 0) * GPAD];
            ulonglong2 a1 = *(const ulonglong2*)&bp[(r + 1) * GPAD];
            ulonglong2 a2 = *(const ulonglong2*)&bp[(r + 2) * GPAD];
            ulonglong2 a3 = *(const ulonglong2*)&bp[(r + 3) * GPAD];
            ulonglong2 b0 = *(const ulonglong2*)&bp[(tx     ) * GPAD];
            ulonglong2 b1 = *(const ulonglong2*)&bp[(tx + 16) * GPAD];
            ulonglong2 b2 = *(const ulonglong2*)&bp[(tx + 32) * GPAD];
            ulonglong2 b3 = *(const ulonglong2*)&bp[(tx + 48) * GPAD];
            fma2(acc[0][0], a0.x, b0.x); fma2(acc[0][1], a0.x, b1.x);
            fma2(acc[0][2], a0.x, b2.x); fma2(acc[0][3], a0.x, b3.x);
            fma2(acc[1][0], a1.x, b0.x); fma2(acc[1][1], a1.x, b1.x);
            fma2(acc[1][2], a1.x, b2.x); fma2(acc[1][3], a1.x, b3.x);
            fma2(acc[2][0], a2.x, b0.x); fma2(acc[2][1], a2.x, b1.x);
            fma2(acc[2][2], a2.x, b2.x); fma2(acc[2][3], a2.x, b3.x);
            fma2(acc[3][0], a3.x, b0.x); fma2(acc[3][1], a3.x, b1.x);
            fma2(acc[3][2], a3.x, b2.x); fma2(acc[3][3], a3.x, b3.x);
            fma2(acc[0][0], a0.y, b0.y); fma2(acc[0][1], a0.y, b1.y);
            fma2(acc[0][2], a0.y, b2.y); fma2(acc[0][3], a0.y, b3.y);
            fma2(acc[1][0], a1.y, b0.y); fma2(acc[1][1], a1.y, b1.y);
            fma2(acc[1][2], a1.y, b2.y); fma2(acc[1][3], a1.y, b3.y);
            fma2(acc[2][0], a2.y, b0.y); fma2(acc[2][1], a2.y, b1.y);
            fma2(acc[2][2], a2.y, b2.y); fma2(acc[2][3], a2.y, b3.y);
            fma2(acc[3][0], a3.y, b0.y); fma2(acc[3][1], a3.y, b1.y);
            fma2(acc[3][2], a3.y, b2.y); fma2(acc[3][3], a3.y, b3.y);
        }

        // channel sums: thread sums quarter-row c = tid>>2, seg (tid&3)*32
        {
            const float* rowp = gsm + (tid >> 2) * GPAD + (tid & 3) * 32;
            float s0 = 0.f, s1 = 0.f, s2 = 0.f, s3 = 0.f;
            #pragma unroll
            for (int q = 0; q < 8; q++) {
                float4 v = *(const float4*)&rowp[q * 4];
                s0 += v.x; s1 += v.y; s2 += v.z; s3 += v.w;
            }
            csum += (s0 + s1) + (s2 + s3);
        }
        __syncthreads();
    }

    // epilogue: horizontal pair-sum + partial Gram store
    float* gp = g_gram_part + (size_t)bid * 4096;
    #pragma unroll
    for (int i = 0; i < 4; i++) {
        #pragma unroll
        for (int q = 0; q < 4; q++) {
            float2 p = unpk(acc[i][q]);
            gp[(r + i) * 64 + tx + 16 * q] = p.x + p.y;
        }
    }
    csum += __shfl_down_sync(0xffffffffu, csum, 2, 4);
    csum += __shfl_down_sync(0xffffffffu, csum, 1, 4);
    if ((tid & 3) == 0) g_sum_part[bid * 64 + (tid >> 2)] = csum;
}

// ================= Kernel 2: deterministic reduction of partials =================
// 129 blocks over NBLK_PAD=448 partials (padding slots are always 0).
__global__ __launch_bounds__(256) void reduce_kernel() {
    __shared__ float s[256];
    const int tid = threadIdx.x;
    if (blockIdx.x < 128) {
        const int e = blockIdx.x * 32 + (tid & 31);
        const int ch = tid >> 5;                           // 0..7, 56 partials each
        const float* base = g_gram_part + (size_t)(ch * 56) * 4096 + e;
        float a0 = 0, a1 = 0, a2 = 0, a3 = 0;
        #pragma unroll 1
        for (int q = 0; q < 56; q += 4) {
            a0 += base[(size_t)(q + 0) * 4096];
            a1 += base[(size_t)(q + 1) * 4096];
            a2 += base[(size_t)(q + 2) * 4096];
            a3 += base[(size_t)(q + 3) * 4096];
        }
        s[tid] = (a0 + a1) + (a2 + a3);
        __syncthreads();
        if (tid < 32) {
            float r = 0.f;
            #pragma unroll
            for (int ch2 = 0; ch2 < 8; ch2++) r += s[ch2 * 32 + tid];
            g_gram[blockIdx.x * 32 + tid] = r;
        }
    } else {
        const int c = tid & 63, ch = tid >> 6;             // 4 chunks x 112 partials
        const float* base = g_sum_part + (size_t)(ch * 112) * 64 + c;
        float a0 = 0, a1 = 0;
        #pragma unroll 1
        for (int q = 0; q < 112; q += 2) {
            a0 += base[(q + 0) * 64];
            a1 += base[(q + 1) * 64];
        }
        s[tid] = a0 + a1;
        __syncthreads();
        if (tid < 64) {
            float r = (s[tid] + s[64 + tid]) + (s[128 + tid] + s[192 + tid]);
            g_mean[tid] = r * (1.0f / (float)Mm);
        }
    }
}

// ================= Kernel 3: Sigma + Newton-Schulz (single block) =================
// Per iteration: phase A computes U = P*P and V = P*S concurrently (shared A-loads,
// 2x ILP), phase B computes W = U*V with the P-update fused. 2 syncs per iteration.
#define SOLVER_SMEM (4 * 4096 * (int)sizeof(float))

__global__ __launch_bounds__(256) void solver_kernel() {
    extern __shared__ float ssm[];
    float* P = ssm;
    float* S = ssm + 4096;
    float* U = ssm + 8192;
    float* V = ssm + 12288;
    const int tid = threadIdx.x;
    const float inv_m = 1.0f / (float)Mm;

    for (int e = tid; e < 4096; e += 256) {
        int c1 = e >> 6, c2 = e & 63;
        S[e] = g_gram[e] * inv_m - g_mean[c1] * g_mean[c2] + ((c1 == c2) ? EPSV : 0.0f);
    }
    __syncthreads();

    float tr = 0.f;
    #pragma unroll
    for (int c = 0; c < 64; c++) tr += S[c * 65];
    const float rTr = 1.0f / tr;
    __syncthreads();

    for (int e = tid; e < 4096; e += 256) {
        S[e] *= rTr;
        int c1 = e >> 6, c2 = e & 63;
        P[e] = (c1 == c2) ? 1.0f : 0.0f;
    }
    __syncthreads();

    const int ty = tid >> 4, tx = tid & 15;
    const int r = ty * 4, cb = tx * 4;

    #pragma unroll 1
    for (int it = 0; it < 5; it++) {
        // ---- phase A: U = P*P and V = P*S, shared A-loads ----
        unsigned long long aU[4][2] = {}, aV[4][2] = {};
        #pragma unroll
        for (int k4 = 0; k4 < 16; k4++) {
            float4 a0 = *(const float4*)&P[(r + 0) * 64 + k4 * 4];
            float4 a1 = *(const float4*)&P[(r + 1) * 64 + k4 * 4];
            float4 a2 = *(const float4*)&P[(r + 2) * 64 + k4 * 4];
            float4 a3 = *(const float4*)&P[(r + 3) * 64 + k4 * 4];
            #pragma unroll
            for (int kk = 0; kk < 4; kk++) {
                float f0 = kk == 0 ? a0.x : kk == 1 ? a0.y : kk == 2 ? a0.z : a0.w;
                float f1 = kk == 0 ? a1.x : kk == 1 ? a1.y : kk == 2 ? a1.z : a1.w;
                float f2 = kk == 0 ? a2.x : kk == 1 ? a2.y : kk == 2 ? a2.z : a2.w;
                float f3 = kk == 0 ? a3.x : kk == 1 ? a3.y : kk == 2 ? a3.z : a3.w;
                const int k = k4 * 4 + kk;
                ulonglong2 bp = *(const ulonglong2*)&P[k * 64 + cb];
                ulonglong2 bs = *(const ulonglong2*)&S[k * 64 + cb];
                unsigned long long d;
                d = dup2(f0);
                fma2(aU[0][0], d, bp.x); fma2(aU[0][1], d, bp.y);
                fma2(aV[0][0], d, bs.x); fma2(aV[0][1], d, bs.y);
                d = dup2(f1);
                fma2(aU[1][0], d, bp.x); fma2(aU[1][1], d, bp.y);
                fma2(aV[1][0], d, bs.x); fma2(aV[1][1], d, bs.y);
                d = dup2(f2);
                fma2(aU[2][0], d, bp.x); fma2(aU[2][1], d, bp.y);
                fma2(aV[2][0], d, bs.x); fma2(aV[2][1], d, bs.y);
                d = dup2(f3);
                fma2(aU[3][0], d, bp.x); fma2(aU[3][1], d, bp.y);
                fma2(aV[3][0], d, bs.x); fma2(aV[3][1], d, bs.y);
            }
        }
        #pragma unroll
        for (int i = 0; i < 4; i++) {
            float2 u0 = unpk(aU[i][0]), u1 = unpk(aU[i][1]);
            float2 v0 = unpk(aV[i][0]), v1 = unpk(aV[i][1]);
            *(float4*)&U[(r + i) * 64 + cb] = make_float4(u0.x, u0.y, u1.x, u1.y);
            *(float4*)&V[(r + i) * 64 + cb] = make_float4(v0.x, v0.y, v1.x, v1.y);
        }
        __syncthreads();

        // ---- phase B: W = U*V, P = 1.5P - 0.5W fused ----
        unsigned long long aW[4][2] = {};
        #pragma unroll
        for (int k4 = 0; k4 < 16; k4++) {
            float4 a0 = *(const float4*)&U[(r + 0) * 64 + k4 * 4];
            float4 a1 = *(const float4*)&U[(r + 1) * 64 + k4 * 4];
            float4 a2 = *(const float4*)&U[(r + 2) * 64 + k4 * 4];
            float4 a3 = *(const float4*)&U[(r + 3) * 64 + k4 * 4];
            #pragma unroll
            for (int kk = 0; kk < 4; kk++) {
                float f0 = kk == 0 ? a0.x : kk == 1 ? a0.y : kk == 2 ? a0.z : a0.w;
                float f1 = kk == 0 ? a1.x : kk == 1 ? a1.y : kk == 2 ? a1.z : a1.w;
                float f2 = kk == 0 ? a2.x : kk == 1 ? a2.y : kk == 2 ? a2.z : a2.w;
                float f3 = kk == 0 ? a3.x : kk == 1 ? a3.y : kk == 2 ? a3.z : a3.w;
                ulonglong2 bv = *(const ulonglong2*)&V[(k4 * 4 + kk) * 64 + cb];
                unsigned long long d;
                d = dup2(f0); fma2(aW[0][0], d, bv.x); fma2(aW[0][1], d, bv.y);
                d = dup2(f1); fma2(aW[1][0], d, bv.x); fma2(aW[1][1], d, bv.y);
                d = dup2(f2); fma2(aW[2][0], d, bv.x); fma2(aW[2][1], d, bv.y);
                d = dup2(f3); fma2(aW[3][0], d, bv.x); fma2(aW[3][1], d, bv.y);
            }
        }
        #pragma unroll
        for (int i = 0; i < 4; i++) {
            float2 w0 = unpk(aW[i][0]), w1 = unpk(aW[i][1]);
            float* pr = &P[(r + i) * 64 + cb];
            float4 pv = *(float4*)pr;
            *(float4*)pr = make_float4(1.5f * pv.x - 0.5f * w0.x,
                                       1.5f * pv.y - 0.5f * w0.y,
                                       1.5f * pv.z - 0.5f * w1.x,
                                       1.5f * pv.w - 0.5f * w1.y);
        }
        __syncthreads();
    }

    const float sq = sqrtf(rTr);
    for (int e = tid; e < 4096; e += 256) {
        int c = e >> 6, cp = e & 63;
        g_wmT[cp * 64 + c] = P[e] * sq;
    }
    if (tid < 64) {
        float bs = 0.f;
        #pragma unroll 8
        for (int cp = 0; cp < 64; cp++) bs += P[tid * 64 + cp] * g_mean[cp];
        g_bias[tid] = bs * sq;
    }
}

// ================= Kernel 4: apply  Y = wm @ X - bias =================
// Grid 444 @ occ 3 (TRUE 3 resident blocks/SM). SINGLE-buffered 64x128 tile
// (smem 48.3 KB): inter-block overlap hides loads, epilogues AND syncs.
// PAIR-OVER-ROWS accumulators: A pairs from wmT[k][c] are direct 64-bit loads.
#define APPLY_SMEM ((4096 + 8192 + 64) * (int)sizeof(float))

__global__ __launch_bounds__(256, 3) void apply_kernel(const float* __restrict__ X,
                                                       float* __restrict__ Y) {
    extern __shared__ float sm[];
    float* s_w = sm;                     // wmT[k][c]          16 KB
    float* s_x = sm + 4096;              // [64][128] tile     32 KB
    float* s_b = sm + 4096 + 8192;       // bias
    const int tid = threadIdx.x;
    const int bid = blockIdx.x;
    const int ts = (bid * NT_A) / NBLK;
    const int te = ((bid + 1) * NT_A) / NBLK;

    #pragma unroll
    for (int itw = 0; itw < 4; itw++) {
        int p = itw * 256 + tid;
        *(float4*)&s_w[p * 4] = *(const float4*)&g_wmT[p * 4];
    }
    if (tid < 64) s_b[tid] = g_bias[tid];

    const uint32_t sx_base = smem_u32(s_x);
    const int c8 = tid >> 5;
    const int j4 = tid & 31;
    const int w = tid >> 5, lane = tid & 31;
    const int r = w * 8, j0 = lane * 4;

    #pragma unroll 1
    for (int i = ts; i < te; i++) {
        {
            int bb = i >> 6, l = (i & 63) << 7;
            const float* Xb = X + (size_t)bb * Cc * Lc + l + j4 * 4;
            #pragma unroll
            for (int itc = 0; itc < 8; itc++) {
                int c = itc * 8 + c8;
                cpasync16(sx_base + (uint32_t)(c * 128 + j4 * 4) * 4,
                          Xb + (size_t)c * Lc);
            }
            CP_COMMIT();
            CP_WAIT(0);
        }
        __syncthreads();

        unsigned long long acc[4][4];      // acc[p][j]: rows (r+2p, r+2p+1), col j0+j
        #pragma unroll
        for (int p = 0; p < 4; p++) { acc[p][0] = acc[p][1] = acc[p][2] = acc[p][3] = 0ull; }

        #pragma unroll 8
        for (int k = 0; k < 64; k++) {
            ulonglong2 aA = *(const ulonglong2*)&s_w[k * 64 + r];      // (r,r+1),(r+2,r+3)
            ulonglong2 aB = *(const ulonglong2*)&s_w[k * 64 + r + 4];  // (r+4,r+5),(r+6,r+7)
            float4 xv = *(const float4*)&s_x[k * 128 + j0];
            unsigned long long d0 = dup2(xv.x), d1 = dup2(xv.y);
            unsigned long long d2 = dup2(xv.z), d3 = dup2(xv.w);
            fma2(acc[0][0], aA.x, d0); fma2(acc[0][1], aA.x, d1);
            fma2(acc[0][2], aA.x, d2); fma2(acc[0][3], aA.x, d3);
            fma2(acc[1][0], aA.y, d0); fma2(acc[1][1], aA.y, d1);
            fma2(acc[1][2], aA.y, d2); fma2(acc[1][3], aA.y, d3);
            fma2(acc[2][0], aB.x, d0); fma2(acc[2][1], aB.x, d1);
            fma2(acc[2][2], aB.x, d2); fma2(acc[2][3], aB.x, d3);
            fma2(acc[3][0], aB.y, d0); fma2(acc[3][1], aB.y, d1);
            fma2(acc[3][2], aB.y, d2); fma2(acc[3][3], aB.y, d3);
        }

        {
            int bb = i >> 6, l = (i & 63) << 7;
            float* Yb = Y + (size_t)bb * Cc * Lc + l + j0;
            #pragma unroll
            for (int p = 0; p < 4; p++) {
                float bb0 = s_b[r + 2 * p], bb1 = s_b[r + 2 * p + 1];
                float2 e0 = unpk(acc[p][0]), e1 = unpk(acc[p][1]);
                float2 e2 = unpk(acc[p][2]), e3 = unpk(acc[p][3]);
                *(float4*)&Yb[(size_t)(r + 2 * p) * Lc] =
                    make_float4(e0.x - bb0, e1.x - bb0, e2.x - bb0, e3.x - bb0);
                *(float4*)&Yb[(size_t)(r + 2 * p + 1) * Lc] =
                    make_float4(e0.y - bb1, e1.y - bb1, e2.y - bb1, e3.y - bb1);
            }
        }
        __syncthreads();   // all reads of s_x done before next tile's loads overwrite
    }
}

// ================= launch =================
extern "C" void kernel_launch(void* const* d_in, const int* in_sizes, int n_in,
                              void* d_out, int out_size) {
    const float* X = (const float*)d_in[0];
    float* Y = (float*)d_out;

    cudaFuncSetAttribute(gram_kernel, cudaFuncAttributeMaxDynamicSharedMemorySize,
                         GRAM_SMEM);
    cudaFuncSetAttribute(apply_kernel, cudaFuncAttributeMaxDynamicSharedMemorySize,
                         APPLY_SMEM);
    cudaFuncSetAttribute(solver_kernel, cudaFuncAttributeMaxDynamicSharedMemorySize,
                         SOLVER_SMEM);

    gram_kernel<<<NBLK, 256, GRAM_SMEM>>>(X);
    reduce_kernel<<<129, 256>>>();
    solver_kernel<<<1, 256, SOLVER_SMEM>>>();
    apply_kernel<<<NBLK, 256, APPLY_SMEM>>>(X, Y);
}

// round 13
// speedup vs baseline: 1.2491x; 1.2491x over previous
#include <cuda_runtime.h>
#include <cstdint>

#define Bb 32
#define Cc 64
#define Lc 8192
#define Mm (Bb * Lc)
#define NBLK 296                 // 148 SMs x 2 resident blocks
#define NT_G 2048                // gram tiles (128 cols each)
#define NT_A 2048                // apply tiles (128 cols each)
#define GPAD 132                 // fp32 stage row stride (floats)
#define ROWB 136                 // bf16 tile row stride (elements) -> 272 B
#define EPSV 1e-5f

__device__ __align__(16) float g_gram_part[NBLK * 4096];
__device__ __align__(16) float g_sum_part[NBLK * 64];
__device__ __align__(16) float g_gram[4096];
__device__ __align__(16) float g_mean[64];
__device__ __align__(16) float g_wmT[4096];
__device__ __align__(16) float g_bias[64];

// ---------------- f32x2 / smem helpers ----------------
__device__ __forceinline__ unsigned long long dup2(float v) {
    unsigned long long r; asm("mov.b64 %0, {%1, %1};" : "=l"(r) : "f"(v)); return r;
}
__device__ __forceinline__ void fma2(unsigned long long& d, unsigned long long a,
                                     unsigned long long b) {
    asm("fma.rn.f32x2 %0, %1, %2, %0;" : "+l"(d) : "l"(a), "l"(b));
}
__device__ __forceinline__ float2 unpk(unsigned long long v) {
    float2 r; asm("mov.b64 {%0, %1}, %2;" : "=f"(r.x), "=f"(r.y) : "l"(v)); return r;
}
__device__ __forceinline__ uint32_t smem_u32(const void* p) {
    uint32_t a;
    asm("{ .reg .u64 t; cvta.to.shared.u64 t, %1; cvt.u32.u64 %0, t; }" : "=r"(a) : "l"(p));
    return a;
}
__device__ __forceinline__ void cpasync16(uint32_t dst, const float* src) {
    asm volatile("cp.async.cg.shared.global [%0], [%1], 16;" :: "r"(dst), "l"(src));
}
#define CP_COMMIT() asm volatile("cp.async.commit_group;" ::: "memory")
#define CP_WAIT(n)  asm volatile("cp.async.wait_group %0;" :: "n"(n) : "memory")

// ---------------- mma.sync helpers (baseline PTX, sm_80+) ----------------
__device__ __forceinline__ void ldsm_x4(uint32_t addr, uint32_t& r0, uint32_t& r1,
                                        uint32_t& r2, uint32_t& r3) {
    asm volatile("ldmatrix.sync.aligned.m8n8.x4.shared.b16 {%0,%1,%2,%3}, [%4];"
                 : "=r"(r0), "=r"(r1), "=r"(r2), "=r"(r3) : "r"(addr));
}
__device__ __forceinline__ void mma16816(float* d, uint32_t a0, uint32_t a1,
                                         uint32_t a2, uint32_t a3,
                                         uint32_t b0, uint32_t b1) {
    asm volatile(
        "mma.sync.aligned.m16n8k16.row.col.f32.bf16.bf16.f32 "
        "{%0,%1,%2,%3}, {%4,%5,%6,%7}, {%8,%9}, {%0,%1,%2,%3};"
        : "+f"(d[0]), "+f"(d[1]), "+f"(d[2]), "+f"(d[3])
        : "r"(a0), "r"(a1), "r"(a2), "r"(a3), "r"(b0), "r"(b1));
}
// pack (lo -> low 16 bits, hi -> high 16 bits)
__device__ __forceinline__ uint32_t bfpack(float lo, float hi) {
    uint32_t r; asm("cvt.rn.bf16x2.f32 %0, %2, %1;" : "=r"(r) : "f"(lo), "f"(hi));
    return r;
}
__device__ __forceinline__ void sts64(uint32_t a, uint32_t v0, uint32_t v1) {
    asm volatile("st.shared.v2.b32 [%0], {%1, %2};" :: "r"(a), "r"(v0), "r"(v1));
}

// ================= Kernel 1: Gram via mma.sync bf16 hi/lo split =================
// Per tile (64ch x 128l): cp.async fp32 stage -> exact bf16 split into a stacked
// 128x128 bf16 matrix (hi rows 0-63, lo rows 64-127, row stride 272B) -> each of
// 8 warps computes a 16x128 band of D = A_stack @ A_stack^T with m16n8k16 HMMA,
// accumulating in registers across all tiles. Epilogue folds the 4 quadrants:
// G = D[hh] + D[hl] + D[lh] + D[ll]  (exact (hi+lo)(hi+lo)^T expansion).
// smem: fp32 stage [64][GPAD] = 33792 B at 0; bf16 tile [128][ROWB] = 34816 B at
// 33792. Epilogue D smem [128][132] fp32 (67584 B) overlays both (dead by then).
#define SMEM_G (33792 + 34816)
#define BF_OFF 33792

__global__ __launch_bounds__(256) void gram_kernel(const float* __restrict__ X) {
    extern __shared__ float gsm[];
    const int tid = threadIdx.x;
    const int lane = tid & 31, w = tid >> 5;
    const int bid = blockIdx.x;
    const int ts = (bid * NT_G) / NBLK;
    const int te = ((bid + 1) * NT_G) / NBLK;

    const uint32_t sbase = smem_u32(gsm);
    const uint32_t bfbase = sbase + BF_OFF;

    // conversion mapping: thread -> channel c (0..63), 32-element l-segment
    const int cc = tid >> 2;
    const int lseg = (tid & 3) * 32;
    const uint32_t hi_addr = bfbase + (uint32_t)(cc * ROWB + lseg) * 2;
    const uint32_t lo_addr = hi_addr + (uint32_t)(64 * ROWB) * 2;

    // mma fragment addresses (row-major [n][k] = the stacked bf16 tile itself)
    const int m0 = w * 16;
    const int arow = m0 + (lane & 7) + ((lane >> 3) & 1) * 8;
    const int acol = (lane >> 4) * 8;
    const uint32_t a_addr = bfbase + (uint32_t)(arow * ROWB + acol) * 2;
    const int brow = (lane & 7) + (lane >> 4) * 8;
    const int bcol = ((lane >> 3) & 1) * 8;
    const uint32_t b_addr = bfbase + (uint32_t)(brow * ROWB + bcol) * 2;

    float acc[16][4];
    #pragma unroll
    for (int t = 0; t < 16; t++) { acc[t][0] = acc[t][1] = acc[t][2] = acc[t][3] = 0.f; }
    float csum = 0.f;

    #pragma unroll 1
    for (int i = ts; i < te; i++) {
        // ---- stage fp32 tile ----
        {
            int bb = i >> 6, l0 = (i & 63) << 7;
            const float* Xb = X + (size_t)bb * (Cc * Lc) + l0;
            #pragma unroll
            for (int it = 0; it < 8; it++) {
                int p = it * 256 + tid, c2 = p >> 5, l4 = p & 31;
                cpasync16(sbase + (uint32_t)(c2 * GPAD + l4 * 4) * 4,
                          Xb + (size_t)c2 * Lc + l4 * 4);
            }
            CP_COMMIT(); CP_WAIT(0);
        }
        __syncthreads();   // stage ready; all warps done with prior tile's mma

        // ---- exact bf16 split: hi rows 0-63, lo rows 64-127 (+ channel sums) ----
        {
            const float* srow = gsm + cc * GPAD + lseg;
            float s0 = 0.f, s1 = 0.f, s2 = 0.f, s3 = 0.f;
            #pragma unroll
            for (int j = 0; j < 8; j++) {
                float4 v = *(const float4*)&srow[j * 4];
                s0 += v.x; s1 += v.y; s2 += v.z; s3 += v.w;
                uint32_t h0 = bfpack(v.x, v.y);
                uint32_t h1 = bfpack(v.z, v.w);
                float r0 = v.x - __uint_as_float(h0 << 16);
                float r1 = v.y - __uint_as_float(h0 & 0xffff0000u);
                float r2 = v.z - __uint_as_float(h1 << 16);
                float r3 = v.w - __uint_as_float(h1 & 0xffff0000u);
                uint32_t q0 = bfpack(r0, r1);
                uint32_t q1 = bfpack(r2, r3);
                sts64(hi_addr + j * 8, h0, h1);
                sts64(lo_addr + j * 8, q0, q1);
            }
            csum += (s0 + s1) + (s2 + s3);
        }
        __syncthreads();   // bf16 tile ready

        // ---- HMMA: warp w computes D rows m0..m0+15, all 128 cols ----
        #pragma unroll
        for (int ks = 0; ks < 8; ks++) {
            const uint32_t koff = (uint32_t)(ks * 32);     // 16 bf16 = 32 B
            uint32_t a0, a1, a2, a3;
            ldsm_x4(a_addr + koff, a0, a1, a2, a3);
            #pragma unroll
            for (int nb = 0; nb < 8; nb++) {
                uint32_t b0, b1, b2, b3;
                ldsm_x4(b_addr + (uint32_t)(nb * 16 * ROWB * 2) + koff, b0, b1, b2, b3);
                mma16816(acc[2 * nb], a0, a1, a2, a3, b0, b1);
                mma16816(acc[2 * nb + 1], a0, a1, a2, a3, b2, b3);
            }
        }
    }

    // ---- epilogue: write D to smem, fold quadrants ----
    __syncthreads();                       // all mma done before overlaying smem
    float* Dsm = gsm;                      // [128][132] fp32
    {
        const int row_in = lane >> 2, kq = lane & 3;
        #pragma unroll
        for (int nt = 0; nt < 16; nt++) {
            float* dr = Dsm + (m0 + row_in) * 132 + nt * 8 + 2 * kq;
            dr[0] = acc[nt][0];
            dr[1] = acc[nt][1];
            dr[132 * 8] = acc[nt][2];
            dr[132 * 8 + 1] = acc[nt][3];
        }
    }
    __syncthreads();
    {
        float* gp = g_gram_part + (size_t)bid * 4096;
        for (int e = tid; e < 4096; e += 256) {
            int c1 = e >> 6, c2 = e & 63;
            gp[e] = (Dsm[c1 * 132 + c2] + Dsm[c1 * 132 + c2 + 64])
                  + (Dsm[(c1 + 64) * 132 + c2] + Dsm[(c1 + 64) * 132 + c2 + 64]);
        }
    }
    csum += __shfl_down_sync(0xffffffffu, csum, 2, 4);
    csum += __shfl_down_sync(0xffffffffu, csum, 1, 4);
    if ((tid & 3) == 0) g_sum_part[bid * 64 + (tid >> 2)] = csum;
}

// ================= Kernel 2: deterministic reduction (296 = 8 x 37) =================
__global__ __launch_bounds__(256) void reduce_kernel() {
    __shared__ float s[256];
    const int tid = threadIdx.x;
    if (blockIdx.x < 128) {
        const int e = blockIdx.x * 32 + (tid & 31);
        const int ch = tid >> 5;
        const float* base = g_gram_part + (size_t)(ch * 37) * 4096 + e;
        float a0 = 0, a1 = 0, a2 = 0, a3 = 0;
        #pragma unroll 1
        for (int q = 0; q < 36; q += 4) {
            a0 += base[(size_t)(q + 0) * 4096];
            a1 += base[(size_t)(q + 1) * 4096];
            a2 += base[(size_t)(q + 2) * 4096];
            a3 += base[(size_t)(q + 3) * 4096];
        }
        a0 += base[(size_t)36 * 4096];
        s[tid] = (a0 + a1) + (a2 + a3);
        __syncthreads();
        if (tid < 32) {
            float r = 0.f;
            #pragma unroll
            for (int c2 = 0; c2 < 8; c2++) r += s[c2 * 32 + tid];
            g_gram[blockIdx.x * 32 + tid] = r;
        }
    } else {
        const int c = tid & 63, ch = tid >> 6;
        const float* base = g_sum_part + (size_t)(ch * 74) * 64 + c;
        float a0 = 0, a1 = 0;
        #pragma unroll 1
        for (int q = 0; q < 74; q += 2) {
            a0 += base[(q + 0) * 64];
            a1 += base[(q + 1) * 64];
        }
        s[tid] = a0 + a1;
        __syncthreads();
        if (tid < 64) {
            float r = (s[tid] + s[64 + tid]) + (s[128 + tid] + s[192 + tid]);
            g_mean[tid] = r * (1.0f / (float)Mm);
        }
    }
}

// ================= Kernel 3: Sigma + Newton-Schulz (single block) =================
#define SOLVER_SMEM (4 * 4096 * (int)sizeof(float))

__global__ __launch_bounds__(256) void solver_kernel() {
    extern __shared__ float ssm[];
    float* P = ssm;
    float* S = ssm + 4096;
    float* U = ssm + 8192;
    float* V = ssm + 12288;
    const int tid = threadIdx.x;
    const float inv_m = 1.0f / (float)Mm;

    for (int e = tid; e < 4096; e += 256) {
        int c1 = e >> 6, c2 = e & 63;
        S[e] = g_gram[e] * inv_m - g_mean[c1] * g_mean[c2] + ((c1 == c2) ? EPSV : 0.0f);
    }
    __syncthreads();
    float tr = 0.f;
    #pragma unroll
    for (int c = 0; c < 64; c++) tr += S[c * 65];
    const float rTr = 1.0f / tr;
    __syncthreads();
    for (int e = tid; e < 4096; e += 256) {
        S[e] *= rTr;
        int c1 = e >> 6, c2 = e & 63;
        P[e] = (c1 == c2) ? 1.0f : 0.0f;
    }
    __syncthreads();

    const int ty = tid >> 4, tx = tid & 15;
    const int r = ty * 4, cb = tx * 4;

    #pragma unroll 1
    for (int it = 0; it < 5; it++) {
        unsigned long long aU[4][2] = {}, aV[4][2] = {};
        #pragma unroll
        for (int k4 = 0; k4 < 16; k4++) {
            float4 a0 = *(const float4*)&P[(r + 0) * 64 + k4 * 4];
            float4 a1 = *(const float4*)&P[(r + 1) * 64 + k4 * 4];
            float4 a2 = *(const float4*)&P[(r + 2) * 64 + k4 * 4];
            float4 a3 = *(const float4*)&P[(r + 3) * 64 + k4 * 4];
            #pragma unroll
            for (int kk = 0; kk < 4; kk++) {
                float f0 = kk == 0 ? a0.x : kk == 1 ? a0.y : kk == 2 ? a0.z : a0.w;
                float f1 = kk == 0 ? a1.x : kk == 1 ? a1.y : kk == 2 ? a1.z : a1.w;
                float f2 = kk == 0 ? a2.x : kk == 1 ? a2.y : kk == 2 ? a2.z : a2.w;
                float f3 = kk == 0 ? a3.x : kk == 1 ? a3.y : kk == 2 ? a3.z : a3.w;
                const int k = k4 * 4 + kk;
                ulonglong2 bp = *(const ulonglong2*)&P[k * 64 + cb];
                ulonglong2 bs = *(const ulonglong2*)&S[k * 64 + cb];
                unsigned long long d;
                d = dup2(f0);
                fma2(aU[0][0], d, bp.x); fma2(aU[0][1], d, bp.y);
                fma2(aV[0][0], d, bs.x); fma2(aV[0][1], d, bs.y);
                d = dup2(f1);
                fma2(aU[1][0], d, bp.x); fma2(aU[1][1], d, bp.y);
                fma2(aV[1][0], d, bs.x); fma2(aV[1][1], d, bs.y);
                d = dup2(f2);
                fma2(aU[2][0], d, bp.x); fma2(aU[2][1], d, bp.y);
                fma2(aV[2][0], d, bs.x); fma2(aV[2][1], d, bs.y);
                d = dup2(f3);
                fma2(aU[3][0], d, bp.x); fma2(aU[3][1], d, bp.y);
                fma2(aV[3][0], d, bs.x); fma2(aV[3][1], d, bs.y);
            }
        }
        #pragma unroll
        for (int i = 0; i < 4; i++) {
            float2 u0 = unpk(aU[i][0]), u1 = unpk(aU[i][1]);
            float2 v0 = unpk(aV[i][0]), v1 = unpk(aV[i][1]);
            *(float4*)&U[(r + i) * 64 + cb] = make_float4(u0.x, u0.y, u1.x, u1.y);
            *(float4*)&V[(r + i) * 64 + cb] = make_float4(v0.x, v0.y, v1.x, v1.y);
        }
        __syncthreads();

        unsigned long long aW[4][2] = {};
        #pragma unroll
        for (int k4 = 0; k4 < 16; k4++) {
            float4 a0 = *(const float4*)&U[(r + 0) * 64 + k4 * 4];
            float4 a1 = *(const float4*)&U[(r + 1) * 64 + k4 * 4];
            float4 a2 = *(const float4*)&U[(r + 2) * 64 + k4 * 4];
            float4 a3 = *(const float4*)&U[(r + 3) * 64 + k4 * 4];
            #pragma unroll
            for (int kk = 0; kk < 4; kk++) {
                float f0 = kk == 0 ? a0.x : kk == 1 ? a0.y : kk == 2 ? a0.z : a0.w;
                float f1 = kk == 0 ? a1.x : kk == 1 ? a1.y : kk == 2 ? a1.z : a1.w;
                float f2 = kk == 0 ? a2.x : kk == 1 ? a2.y : kk == 2 ? a2.z : a2.w;
                float f3 = kk == 0 ? a3.x : kk == 1 ? a3.y : kk == 2 ? a3.z : a3.w;
                ulonglong2 bv = *(const ulonglong2*)&V[(k4 * 4 + kk) * 64 + cb];
                unsigned long long d;
                d = dup2(f0); fma2(aW[0][0], d, bv.x); fma2(aW[0][1], d, bv.y);
                d = dup2(f1); fma2(aW[1][0], d, bv.x); fma2(aW[1][1], d, bv.y);
                d = dup2(f2); fma2(aW[2][0], d, bv.x); fma2(aW[2][1], d, bv.y);
                d = dup2(f3); fma2(aW[3][0], d, bv.x); fma2(aW[3][1], d, bv.y);
            }
        }
        #pragma unroll
        for (int i = 0; i < 4; i++) {
            float2 w0 = unpk(aW[i][0]), w1 = unpk(aW[i][1]);
            float* pr = &P[(r + i) * 64 + cb];
            float4 pv = *(float4*)pr;
            *(float4*)pr = make_float4(1.5f * pv.x - 0.5f * w0.x,
                                       1.5f * pv.y - 0.5f * w0.y,
                                       1.5f * pv.z - 0.5f * w1.x,
                                       1.5f * pv.w - 0.5f * w1.y);
        }
        __syncthreads();
    }

    const float sq = sqrtf(rTr);
    for (int e = tid; e < 4096; e += 256) {
        int c = e >> 6, cp = e & 63;
        g_wmT[cp * 64 + c] = P[e] * sq;
    }
    if (tid < 64) {
        float bs = 0.f;
        #pragma unroll 8
        for (int cp = 0; cp < 64; cp++) bs += P[tid * 64 + cp] * g_mean[cp];
        g_bias[tid] = bs * sq;
    }
}

// ================= Kernel 4: apply (round-8 best: 46.3us) =================
#define APPLY_SMEM ((4096 + 2 * 8192 + 64) * (int)sizeof(float))

__global__ __launch_bounds__(256, 2) void apply_kernel(const float* __restrict__ X,
                                                       float* __restrict__ Y) {
    extern __shared__ float sm[];
    float* s_w = sm;
    float* s_x = sm + 4096;
    float* s_b = sm + 4096 + 16384;
    const int tid = threadIdx.x;
    const int bid = blockIdx.x;
    const int ts = (bid * NT_A) / NBLK;
    const int te = ((bid + 1) * NT_A) / NBLK;

    #pragma unroll
    for (int itw = 0; itw < 4; itw++) {
        int p = itw * 256 + tid;
        *(float4*)&s_w[p * 4] = *(const float4*)&g_wmT[p * 4];
    }
    if (tid < 64) s_b[tid] = g_bias[tid];

    const uint32_t sx_base = smem_u32(s_x);
    const int c8 = tid >> 5;
    const int j4 = tid & 31;

    {
        int bb = ts >> 6, l = (ts & 63) << 7;
        const float* Xb = X + (size_t)bb * Cc * Lc + l + j4 * 4;
        #pragma unroll
        for (int itc = 0; itc < 8; itc++) {
            int c = itc * 8 + c8;
            cpasync16(sx_base + (uint32_t)(c * 128 + j4 * 4) * 4, Xb + (size_t)c * Lc);
        }
        CP_COMMIT();
    }

    const int w = tid >> 5, lane = tid & 31;
    const int r = w * 8, j0 = lane * 4;

    #pragma unroll 1
    for (int i = ts; i < te; i++) {
        const int cur = (i - ts) & 1;
        if (i + 1 < te) {
            int bb = (i + 1) >> 6, l = ((i + 1) & 63) << 7;
            const float* Xb = X + (size_t)bb * Cc * Lc + l + j4 * 4;
            const uint32_t dst0 = sx_base + (uint32_t)((1 - cur) * 8192) * 4;
            #pragma unroll
            for (int itc = 0; itc < 8; itc++) {
                int c = itc * 8 + c8;
                cpasync16(dst0 + (uint32_t)(c * 128 + j4 * 4) * 4, Xb + (size_t)c * Lc);
            }
            CP_COMMIT();
            CP_WAIT(1);
        } else {
            CP_WAIT(0);
        }
        __syncthreads();

        const float* xb = s_x + cur * 8192;
        unsigned long long acc[4][4];
        #pragma unroll
        for (int p = 0; p < 4; p++) { acc[p][0] = acc[p][1] = acc[p][2] = acc[p][3] = 0ull; }

        #pragma unroll 8
        for (int k = 0; k < 64; k++) {
            ulonglong2 aA = *(const ulonglong2*)&s_w[k * 64 + r];
            ulonglong2 aB = *(const ulonglong2*)&s_w[k * 64 + r + 4];
            float4 xv = *(const float4*)&xb[k * 128 + j0];
            unsigned long long d0 = dup2(xv.x), d1 = dup2(xv.y);
            unsigned long long d2 = dup2(xv.z), d3 = dup2(xv.w);
            fma2(acc[0][0], aA.x, d0); fma2(acc[0][1], aA.x, d1);
            fma2(acc[0][2], aA.x, d2); fma2(acc[0][3], aA.x, d3);
            fma2(acc[1][0], aA.y, d0); fma2(acc[1][1], aA.y, d1);
            fma2(acc[1][2], aA.y, d2); fma2(acc[1][3], aA.y, d3);
            fma2(acc[2][0], aB.x, d0); fma2(acc[2][1], aB.x, d1);
            fma2(acc[2][2], aB.x, d2); fma2(acc[2][3], aB.x, d3);
            fma2(acc[3][0], aB.y, d0); fma2(acc[3][1], aB.y, d1);
            fma2(acc[3][2], aB.y, d2); fma2(acc[3][3], aB.y, d3);
        }

        {
            int bb = i >> 6, l = (i & 63) << 7;
            float* Yb = Y + (size_t)bb * Cc * Lc + l + j0;
            #pragma unroll
            for (int p = 0; p < 4; p++) {
                float bb0 = s_b[r + 2 * p], bb1 = s_b[r + 2 * p + 1];
                float2 e0 = unpk(acc[p][0]), e1 = unpk(acc[p][1]);
                float2 e2 = unpk(acc[p][2]), e3 = unpk(acc[p][3]);
                *(float4*)&Yb[(size_t)(r + 2 * p) * Lc] =
                    make_float4(e0.x - bb0, e1.x - bb0, e2.x - bb0, e3.x - bb0);
                *(float4*)&Yb[(size_t)(r + 2 * p + 1) * Lc] =
                    make_float4(e0.y - bb1, e1.y - bb1, e2.y - bb1, e3.y - bb1);
            }
        }
        __syncthreads();
    }
}

// ================= launch =================
extern "C" void kernel_launch(void* const* d_in, const int* in_sizes, int n_in,
                              void* d_out, int out_size) {
    const float* X = (const float*)d_in[0];
    float* Y = (float*)d_out;

    cudaFuncSetAttribute(gram_kernel, cudaFuncAttributeMaxDynamicSharedMemorySize,
                         SMEM_G);
    cudaFuncSetAttribute(apply_kernel, cudaFuncAttributeMaxDynamicSharedMemorySize,
                         APPLY_SMEM);
    cudaFuncSetAttribute(solver_kernel, cudaFuncAttributeMaxDynamicSharedMemorySize,
                         SOLVER_SMEM);

    gram_kernel<<<NBLK, 256, SMEM_G>>>(X);
    reduce_kernel<<<129, 256>>>();
    solver_kernel<<<1, 256, SOLVER_SMEM>>>();
    apply_kernel<<<NBLK, 256, APPLY_SMEM>>>(X, Y);
}

// round 14
// speedup vs baseline: 1.2767x; 1.0221x over previous
#include <cuda_runtime.h>
#include <cuda_bf16.h>
#include <cstdint>

#define Bb 32
#define Cc 64
#define Lc 8192
#define Mm (Bb * Lc)
#define NBLK 296                 // 148 SMs x 2 resident blocks
#define NT_G 2048                // gram tiles (128 cols each)
#define NT_A 2048                // apply tiles (128 cols each)
#define GPAD 132                 // fp32 stage row stride (floats)
#define ROWB 136                 // bf16 tile row stride (elements) -> 272 B
#define WROW 264                 // wmDual smem row stride (bf16 elements)
#define EPSV 1e-5f

__device__ __align__(16) float g_gram_part[NBLK * 4096];
__device__ __align__(16) float g_sum_part[NBLK * 64];
__device__ __align__(16) float g_gram[4096];
__device__ __align__(16) float g_mean[64];
__device__ __align__(16) __nv_bfloat16 g_wmDual[64 * 256];   // [c][ wh | wl | wl | wh ]
__device__ __align__(16) float g_bias[64];

// ---------------- f32x2 / smem helpers ----------------
__device__ __forceinline__ unsigned long long dup2(float v) {
    unsigned long long r; asm("mov.b64 %0, {%1, %1};" : "=l"(r) : "f"(v)); return r;
}
__device__ __forceinline__ void fma2(unsigned long long& d, unsigned long long a,
                                     unsigned long long b) {
    asm("fma.rn.f32x2 %0, %1, %2, %0;" : "+l"(d) : "l"(a), "l"(b));
}
__device__ __forceinline__ float2 unpk(unsigned long long v) {
    float2 r; asm("mov.b64 {%0, %1}, %2;" : "=f"(r.x), "=f"(r.y) : "l"(v)); return r;
}
__device__ __forceinline__ uint32_t smem_u32(const void* p) {
    uint32_t a;
    asm("{ .reg .u64 t; cvta.to.shared.u64 t, %1; cvt.u32.u64 %0, t; }" : "=r"(a) : "l"(p));
    return a;
}
__device__ __forceinline__ void cpasync16(uint32_t dst, const float* src) {
    asm volatile("cp.async.cg.shared.global [%0], [%1], 16;" :: "r"(dst), "l"(src));
}
#define CP_COMMIT() asm volatile("cp.async.commit_group;" ::: "memory")
#define CP_WAIT(n)  asm volatile("cp.async.wait_group %0;" :: "n"(n) : "memory")

// ---------------- mma.sync helpers (baseline PTX, sm_80+) ----------------
__device__ __forceinline__ void ldsm_x4(uint32_t addr, uint32_t& r0, uint32_t& r1,
                                        uint32_t& r2, uint32_t& r3) {
    asm volatile("ldmatrix.sync.aligned.m8n8.x4.shared.b16 {%0,%1,%2,%3}, [%4];"
                 : "=r"(r0), "=r"(r1), "=r"(r2), "=r"(r3) : "r"(addr));
}
__device__ __forceinline__ void ldsm_x4t(uint32_t addr, uint32_t& r0, uint32_t& r1,
                                         uint32_t& r2, uint32_t& r3) {
    asm volatile("ldmatrix.sync.aligned.m8n8.x4.trans.shared.b16 {%0,%1,%2,%3}, [%4];"
                 : "=r"(r0), "=r"(r1), "=r"(r2), "=r"(r3) : "r"(addr));
}
__device__ __forceinline__ void mma16816(float* d, uint32_t a0, uint32_t a1,
                                         uint32_t a2, uint32_t a3,
                                         uint32_t b0, uint32_t b1) {
    asm volatile(
        "mma.sync.aligned.m16n8k16.row.col.f32.bf16.bf16.f32 "
        "{%0,%1,%2,%3}, {%4,%5,%6,%7}, {%8,%9}, {%0,%1,%2,%3};"
        : "+f"(d[0]), "+f"(d[1]), "+f"(d[2]), "+f"(d[3])
        : "r"(a0), "r"(a1), "r"(a2), "r"(a3), "r"(b0), "r"(b1));
}
__device__ __forceinline__ uint32_t bfpack(float lo, float hi) {
    uint32_t r; asm("cvt.rn.bf16x2.f32 %0, %2, %1;" : "=r"(r) : "f"(lo), "f"(hi));
    return r;
}
__device__ __forceinline__ void sts64(uint32_t a, uint32_t v0, uint32_t v1) {
    asm volatile("st.shared.v2.b32 [%0], {%1, %2};" :: "r"(a), "r"(v0), "r"(v1));
}

// ================= Kernel 1: Gram via mma.sync (round-13, unchanged) =================
#define SMEM_G (33792 + 34816)
#define BF_OFF 33792

__global__ __launch_bounds__(256) void gram_kernel(const float* __restrict__ X) {
    extern __shared__ float gsm[];
    const int tid = threadIdx.x;
    const int lane = tid & 31, w = tid >> 5;
    const int bid = blockIdx.x;
    const int ts = (bid * NT_G) / NBLK;
    const int te = ((bid + 1) * NT_G) / NBLK;

    const uint32_t sbase = smem_u32(gsm);
    const uint32_t bfbase = sbase + BF_OFF;

    const int cc = tid >> 2;
    const int lseg = (tid & 3) * 32;
    const uint32_t hi_addr = bfbase + (uint32_t)(cc * ROWB + lseg) * 2;
    const uint32_t lo_addr = hi_addr + (uint32_t)(64 * ROWB) * 2;

    const int m0 = w * 16;
    const int arow = m0 + (lane & 7) + ((lane >> 3) & 1) * 8;
    const int acol = (lane >> 4) * 8;
    const uint32_t a_addr = bfbase + (uint32_t)(arow * ROWB + acol) * 2;
    const int brow = (lane & 7) + (lane >> 4) * 8;
    const int bcol = ((lane >> 3) & 1) * 8;
    const uint32_t b_addr = bfbase + (uint32_t)(brow * ROWB + bcol) * 2;

    float acc[16][4];
    #pragma unroll
    for (int t = 0; t < 16; t++) { acc[t][0] = acc[t][1] = acc[t][2] = acc[t][3] = 0.f; }
    float csum = 0.f;

    #pragma unroll 1
    for (int i = ts; i < te; i++) {
        {
            int bb = i >> 6, l0 = (i & 63) << 7;
            const float* Xb = X + (size_t)bb * (Cc * Lc) + l0;
            #pragma unroll
            for (int it = 0; it < 8; it++) {
                int p = it * 256 + tid, c2 = p >> 5, l4 = p & 31;
                cpasync16(sbase + (uint32_t)(c2 * GPAD + l4 * 4) * 4,
                          Xb + (size_t)c2 * Lc + l4 * 4);
            }
            CP_COMMIT(); CP_WAIT(0);
        }
        __syncthreads();

        {
            const float* srow = gsm + cc * GPAD + lseg;
            float s0 = 0.f, s1 = 0.f, s2 = 0.f, s3 = 0.f;
            #pragma unroll
            for (int j = 0; j < 8; j++) {
                float4 v = *(const float4*)&srow[j * 4];
                s0 += v.x; s1 += v.y; s2 += v.z; s3 += v.w;
                uint32_t h0 = bfpack(v.x, v.y);
                uint32_t h1 = bfpack(v.z, v.w);
                float r0 = v.x - __uint_as_float(h0 << 16);
                float r1 = v.y - __uint_as_float(h0 & 0xffff0000u);
                float r2 = v.z - __uint_as_float(h1 << 16);
                float r3 = v.w - __uint_as_float(h1 & 0xffff0000u);
                uint32_t q0 = bfpack(r0, r1);
                uint32_t q1 = bfpack(r2, r3);
                sts64(hi_addr + j * 8, h0, h1);
                sts64(lo_addr + j * 8, q0, q1);
            }
            csum += (s0 + s1) + (s2 + s3);
        }
        __syncthreads();

        #pragma unroll
        for (int ks = 0; ks < 8; ks++) {
            const uint32_t koff = (uint32_t)(ks * 32);
            uint32_t a0, a1, a2, a3;
            ldsm_x4(a_addr + koff, a0, a1, a2, a3);
            #pragma unroll
            for (int nb = 0; nb < 8; nb++) {
                uint32_t b0, b1, b2, b3;
                ldsm_x4(b_addr + (uint32_t)(nb * 16 * ROWB * 2) + koff, b0, b1, b2, b3);
                mma16816(acc[2 * nb], a0, a1, a2, a3, b0, b1);
                mma16816(acc[2 * nb + 1], a0, a1, a2, a3, b2, b3);
            }
        }
    }

    __syncthreads();
    float* Dsm = gsm;
    {
        const int row_in = lane >> 2, kq = lane & 3;
        #pragma unroll
        for (int nt = 0; nt < 16; nt++) {
            float* dr = Dsm + (m0 + row_in) * 132 + nt * 8 + 2 * kq;
            dr[0] = acc[nt][0];
            dr[1] = acc[nt][1];
            dr[132 * 8] = acc[nt][2];
            dr[132 * 8 + 1] = acc[nt][3];
        }
    }
    __syncthreads();
    {
        float* gp = g_gram_part + (size_t)bid * 4096;
        for (int e = tid; e < 4096; e += 256) {
            int c1 = e >> 6, c2 = e & 63;
            gp[e] = (Dsm[c1 * 132 + c2] + Dsm[c1 * 132 + c2 + 64])
                  + (Dsm[(c1 + 64) * 132 + c2] + Dsm[(c1 + 64) * 132 + c2 + 64]);
        }
    }
    csum += __shfl_down_sync(0xffffffffu, csum, 2, 4);
    csum += __shfl_down_sync(0xffffffffu, csum, 1, 4);
    if ((tid & 3) == 0) g_sum_part[bid * 64 + (tid >> 2)] = csum;
}

// ================= Kernel 2: reduction (unchanged) =================
__global__ __launch_bounds__(256) void reduce_kernel() {
    __shared__ float s[256];
    const int tid = threadIdx.x;
    if (blockIdx.x < 128) {
        const int e = blockIdx.x * 32 + (tid & 31);
        const int ch = tid >> 5;
        const float* base = g_gram_part + (size_t)(ch * 37) * 4096 + e;
        float a0 = 0, a1 = 0, a2 = 0, a3 = 0;
        #pragma unroll 1
        for (int q = 0; q < 36; q += 4) {
            a0 += base[(size_t)(q + 0) * 4096];
            a1 += base[(size_t)(q + 1) * 4096];
            a2 += base[(size_t)(q + 2) * 4096];
            a3 += base[(size_t)(q + 3) * 4096];
        }
        a0 += base[(size_t)36 * 4096];
        s[tid] = (a0 + a1) + (a2 + a3);
        __syncthreads();
        if (tid < 32) {
            float r = 0.f;
            #pragma unroll
            for (int c2 = 0; c2 < 8; c2++) r += s[c2 * 32 + tid];
            g_gram[blockIdx.x * 32 + tid] = r;
        }
    } else {
        const int c = tid & 63, ch = tid >> 6;
        const float* base = g_sum_part + (size_t)(ch * 74) * 64 + c;
        float a0 = 0, a1 = 0;
        #pragma unroll 1
        for (int q = 0; q < 74; q += 2) {
            a0 += base[(q + 0) * 64];
            a1 += base[(q + 1) * 64];
        }
        s[tid] = a0 + a1;
        __syncthreads();
        if (tid < 64) {
            float r = (s[tid] + s[64 + tid]) + (s[128 + tid] + s[192 + tid]);
            g_mean[tid] = r * (1.0f / (float)Mm);
        }
    }
}

// ================= Kernel 3: Sigma + Newton-Schulz (+ wmDual emit) =================
#define SOLVER_SMEM (4 * 4096 * (int)sizeof(float))

__global__ __launch_bounds__(256) void solver_kernel() {
    extern __shared__ float ssm[];
    float* P = ssm;
    float* S = ssm + 4096;
    float* U = ssm + 8192;
    float* V = ssm + 12288;
    const int tid = threadIdx.x;
    const float inv_m = 1.0f / (float)Mm;

    for (int e = tid; e < 4096; e += 256) {
        int c1 = e >> 6, c2 = e & 63;
        S[e] = g_gram[e] * inv_m - g_mean[c1] * g_mean[c2] + ((c1 == c2) ? EPSV : 0.0f);
    }
    __syncthreads();
    float tr = 0.f;
    #pragma unroll
    for (int c = 0; c < 64; c++) tr += S[c * 65];
    const float rTr = 1.0f / tr;
    __syncthreads();
    for (int e = tid; e < 4096; e += 256) {
        S[e] *= rTr;
        int c1 = e >> 6, c2 = e & 63;
        P[e] = (c1 == c2) ? 1.0f : 0.0f;
    }
    __syncthreads();

    const int ty = tid >> 4, tx = tid & 15;
    const int r = ty * 4, cb = tx * 4;

    #pragma unroll 1
    for (int it = 0; it < 5; it++) {
        unsigned long long aU[4][2] = {}, aV[4][2] = {};
        #pragma unroll
        for (int k4 = 0; k4 < 16; k4++) {
            float4 a0 = *(const float4*)&P[(r + 0) * 64 + k4 * 4];
            float4 a1 = *(const float4*)&P[(r + 1) * 64 + k4 * 4];
            float4 a2 = *(const float4*)&P[(r + 2) * 64 + k4 * 4];
            float4 a3 = *(const float4*)&P[(r + 3) * 64 + k4 * 4];
            #pragma unroll
            for (int kk = 0; kk < 4; kk++) {
                float f0 = kk == 0 ? a0.x : kk == 1 ? a0.y : kk == 2 ? a0.z : a0.w;
                float f1 = kk == 0 ? a1.x : kk == 1 ? a1.y : kk == 2 ? a1.z : a1.w;
                float f2 = kk == 0 ? a2.x : kk == 1 ? a2.y : kk == 2 ? a2.z : a2.w;
                float f3 = kk == 0 ? a3.x : kk == 1 ? a3.y : kk == 2 ? a3.z : a3.w;
                const int k = k4 * 4 + kk;
                ulonglong2 bp = *(const ulonglong2*)&P[k * 64 + cb];
                ulonglong2 bs = *(const ulonglong2*)&S[k * 64 + cb];
                unsigned long long d;
                d = dup2(f0);
                fma2(aU[0][0], d, bp.x); fma2(aU[0][1], d, bp.y);
                fma2(aV[0][0], d, bs.x); fma2(aV[0][1], d, bs.y);
                d = dup2(f1);
                fma2(aU[1][0], d, bp.x); fma2(aU[1][1], d, bp.y);
                fma2(aV[1][0], d, bs.x); fma2(aV[1][1], d, bs.y);
                d = dup2(f2);
                fma2(aU[2][0], d, bp.x); fma2(aU[2][1], d, bp.y);
                fma2(aV[2][0], d, bs.x); fma2(aV[2][1], d, bs.y);
                d = dup2(f3);
                fma2(aU[3][0], d, bp.x); fma2(aU[3][1], d, bp.y);
                fma2(aV[3][0], d, bs.x); fma2(aV[3][1], d, bs.y);
            }
        }
        #pragma unroll
        for (int i = 0; i < 4; i++) {
            float2 u0 = unpk(aU[i][0]), u1 = unpk(aU[i][1]);
            float2 v0 = unpk(aV[i][0]), v1 = unpk(aV[i][1]);
            *(float4*)&U[(r + i) * 64 + cb] = make_float4(u0.x, u0.y, u1.x, u1.y);
            *(float4*)&V[(r + i) * 64 + cb] = make_float4(v0.x, v0.y, v1.x, v1.y);
        }
        __syncthreads();

        unsigned long long aW[4][2] = {};
        #pragma unroll
        for (int k4 = 0; k4 < 16; k4++) {
            float4 a0 = *(const float4*)&U[(r + 0) * 64 + k4 * 4];
            float4 a1 = *(const float4*)&U[(r + 1) * 64 + k4 * 4];
            float4 a2 = *(const float4*)&U[(r + 2) * 64 + k4 * 4];
            float4 a3 = *(const float4*)&U[(r + 3) * 64 + k4 * 4];
            #pragma unroll
            for (int kk = 0; kk < 4; kk++) {
                float f0 = kk == 0 ? a0.x : kk == 1 ? a0.y : kk == 2 ? a0.z : a0.w;
                float f1 = kk == 0 ? a1.x : kk == 1 ? a1.y : kk == 2 ? a1.z : a1.w;
                float f2 = kk == 0 ? a2.x : kk == 1 ? a2.y : kk == 2 ? a2.z : a2.w;
                float f3 = kk == 0 ? a3.x : kk == 1 ? a3.y : kk == 2 ? a3.z : a3.w;
                ulonglong2 bv = *(const ulonglong2*)&V[(k4 * 4 + kk) * 64 + cb];
                unsigned long long d;
                d = dup2(f0); fma2(aW[0][0], d, bv.x); fma2(aW[0][1], d, bv.y);
                d = dup2(f1); fma2(aW[1][0], d, bv.x); fma2(aW[1][1], d, bv.y);
                d = dup2(f2); fma2(aW[2][0], d, bv.x); fma2(aW[2][1], d, bv.y);
                d = dup2(f3); fma2(aW[3][0], d, bv.x); fma2(aW[3][1], d, bv.y);
            }
        }
        #pragma unroll
        for (int i = 0; i < 4; i++) {
            float2 w0 = unpk(aW[i][0]), w1 = unpk(aW[i][1]);
            float* pr = &P[(r + i) * 64 + cb];
            float4 pv = *(float4*)pr;
            *(float4*)pr = make_float4(1.5f * pv.x - 0.5f * w0.x,
                                       1.5f * pv.y - 0.5f * w0.y,
                                       1.5f * pv.z - 0.5f * w1.x,
                                       1.5f * pv.w - 0.5f * w1.y);
        }
        __syncthreads();
    }

    const float sq = sqrtf(rTr);
    // emit wmDual: [c][ wh(0:64) | wl(64:128) | wl(128:192) | wh(192:256) ]
    for (int e = tid; e < 4096; e += 256) {
        int c = e >> 6, k = e & 63;
        float wv = P[c * 64 + k] * sq;
        __nv_bfloat16 h = __float2bfloat16(wv);
        __nv_bfloat16 l = __float2bfloat16(wv - __bfloat162float(h));
        g_wmDual[c * 256 + k] = h;
        g_wmDual[c * 256 + 64 + k] = l;
        g_wmDual[c * 256 + 128 + k] = l;
        g_wmDual[c * 256 + 192 + k] = h;
    }
    if (tid < 64) {
        float bs = 0.f;
        #pragma unroll 8
        for (int cp = 0; cp < 64; cp++) bs += P[tid * 64 + cp] * g_mean[cp];
        g_bias[tid] = bs * sq;
    }
}

// ================= Kernel 4: apply via mma.sync dual-stack =================
// Per tile (64ch x 128l): stage fp32 -> stacked bf16 B [k=128][n=128] (hi rows
// 0-63, lo rows 64-127, stride ROWB) -> Y = wmDual-chain1 + chain2 (exact full
// product). 8 warps: warp w = (m-tile w&3, n-half w>>2). Per phys k-step: 4 B
// ldsm.x4.trans (reused by both chains) + 2 A ldsm.x4 + 16 mma. Epilogue writes
// Y fragments minus bias straight to global.
// smem: stage 33792B @0; wmDual [64][WROW] bf16 = 33792B @33792; B [128][ROWB]
// bf16 = 34816B @67584; bias 256B @102400. Total 102656B (occ 2).
#define WS_OFF 33792
#define BT_OFF 67584
#define BIAS_OFF 102400
#define SMEM_A2 102656

__global__ __launch_bounds__(256) void apply_kernel(const float* __restrict__ X,
                                                    float* __restrict__ Y) {
    extern __shared__ float sm[];
    const int tid = threadIdx.x;
    const int lane = tid & 31, w = tid >> 5;
    const int bid = blockIdx.x;
    const int ts = (bid * NT_A) / NBLK;
    const int te = ((bid + 1) * NT_A) / NBLK;

    const uint32_t sbase = smem_u32(sm);
    const uint32_t wsm = sbase + WS_OFF;
    const uint32_t bsm = sbase + BT_OFF;
    float* s_b = (float*)((char*)sm + BIAS_OFF);

    // prologue: wmDual global -> smem (row stride WROW), bias
    {
        const uint32_t* src = (const uint32_t*)g_wmDual;   // 8192 u32
        #pragma unroll
        for (int it = 0; it < 32; it++) {
            int idx = it * 256 + tid;
            int row = idx >> 7, col2 = idx & 127;
            uint32_t v = src[idx];
            asm volatile("st.shared.b32 [%0], %1;"
                         :: "r"(wsm + (uint32_t)(row * (WROW / 2) + col2) * 4), "r"(v));
        }
        if (tid < 64) s_b[tid] = g_bias[tid];
    }

    // conversion mapping
    const int cc = tid >> 2;
    const int lseg = (tid & 3) * 32;
    const uint32_t hi_addr = bsm + (uint32_t)(cc * ROWB + lseg) * 2;
    const uint32_t lo_addr = hi_addr + (uint32_t)(64 * ROWB) * 2;

    // mma mapping
    const int m0 = (w & 3) * 16;
    const int n0 = (w >> 2) * 64;
    const int frow = (lane & 7) + ((lane >> 3) & 1) * 8;   // row-within-16 pattern
    const int fcol8 = (lane >> 4) * 8;
    const uint32_t a_base = wsm + (uint32_t)((m0 + frow) * WROW + fcol8) * 2;
    const uint32_t b_base = bsm + (uint32_t)(frow * ROWB + n0 + fcol8) * 2;

    __syncthreads();

    #pragma unroll 1
    for (int i = ts; i < te; i++) {
        const int bb = i >> 6, l0 = (i & 63) << 7;
        // ---- stage fp32 tile ----
        {
            const float* Xb = X + (size_t)bb * (Cc * Lc) + l0;
            #pragma unroll
            for (int it = 0; it < 8; it++) {
                int p = it * 256 + tid, c2 = p >> 5, l4 = p & 31;
                cpasync16(sbase + (uint32_t)(c2 * GPAD + l4 * 4) * 4,
                          Xb + (size_t)c2 * Lc + l4 * 4);
            }
            CP_COMMIT(); CP_WAIT(0);
        }
        __syncthreads();

        // ---- exact bf16 split into stacked B ----
        {
            const float* srow = sm + cc * GPAD + lseg;
            #pragma unroll
            for (int j = 0; j < 8; j++) {
                float4 v = *(const float4*)&srow[j * 4];
                uint32_t h0 = bfpack(v.x, v.y);
                uint32_t h1 = bfpack(v.z, v.w);
                float r0 = v.x - __uint_as_float(h0 << 16);
                float r1 = v.y - __uint_as_float(h0 & 0xffff0000u);
                float r2 = v.z - __uint_as_float(h1 << 16);
                float r3 = v.w - __uint_as_float(h1 & 0xffff0000u);
                uint32_t q0 = bfpack(r0, r1);
                uint32_t q1 = bfpack(r2, r3);
                sts64(hi_addr + j * 8, h0, h1);
                sts64(lo_addr + j * 8, q0, q1);
            }
        }
        __syncthreads();

        // ---- HMMA: 8 phys k-steps x (4 B-ldsm + 2 A-ldsm + 16 mma) ----
        float acc[8][4];
        #pragma unroll
        for (int t = 0; t < 8; t++) { acc[t][0] = acc[t][1] = acc[t][2] = acc[t][3] = 0.f; }

        #pragma unroll
        for (int kp = 0; kp < 8; kp++) {
            uint32_t bq[8][2];
            #pragma unroll
            for (int nb = 0; nb < 4; nb++) {
                uint32_t b0, b1, b2, b3;
                ldsm_x4t(b_base + (uint32_t)(kp * 16 * ROWB + nb * 16) * 2,
                         b0, b1, b2, b3);
                bq[2 * nb][0] = b0; bq[2 * nb][1] = b1;
                bq[2 * nb + 1][0] = b2; bq[2 * nb + 1][1] = b3;
            }
            uint32_t a0, a1, a2, a3, c0, c1, c2, c3;
            ldsm_x4(a_base + (uint32_t)(kp * 16) * 2, a0, a1, a2, a3);
            ldsm_x4(a_base + (uint32_t)(128 + kp * 16) * 2, c0, c1, c2, c3);
            #pragma unroll
            for (int j = 0; j < 8; j++) {
                mma16816(acc[j], a0, a1, a2, a3, bq[j][0], bq[j][1]);
                mma16816(acc[j], c0, c1, c2, c3, bq[j][0], bq[j][1]);
            }
        }

        // ---- epilogue: Y fragments - bias ----
        {
            const int r0 = m0 + (lane >> 2);
            const float bb0 = s_b[r0], bb1 = s_b[r0 + 8];
            float* Yb = Y + (size_t)bb * (Cc * Lc) + l0 + n0 + 2 * (lane & 3);
            float* y0 = Yb + (size_t)r0 * Lc;
            float* y1 = Yb + (size_t)(r0 + 8) * Lc;
            #pragma unroll
            for (int j = 0; j < 8; j++) {
                *(float2*)&y0[j * 8] = make_float2(acc[j][0] - bb0, acc[j][1] - bb0);
                *(float2*)&y1[j * 8] = make_float2(acc[j][2] - bb1, acc[j][3] - bb1);
            }
        }
        __syncthreads();   // B smem reused next tile
    }
}

// ================= launch =================
extern "C" void kernel_launch(void* const* d_in, const int* in_sizes, int n_in,
                              void* d_out, int out_size) {
    const float* X = (const float*)d_in[0];
    float* Y = (float*)d_out;

    cudaFuncSetAttribute(gram_kernel, cudaFuncAttributeMaxDynamicSharedMemorySize,
                         SMEM_G);
    cudaFuncSetAttribute(apply_kernel, cudaFuncAttributeMaxDynamicSharedMemorySize,
                         SMEM_A2);
    cudaFuncSetAttribute(solver_kernel, cudaFuncAttributeMaxDynamicSharedMemorySize,
                         SOLVER_SMEM);

    gram_kernel<<<NBLK, 256, SMEM_G>>>(X);
    reduce_kernel<<<129, 256>>>();
    solver_kernel<<<1, 256, SOLVER_SMEM>>>();
    apply_kernel<<<NBLK, 256, SMEM_A2>>>(X, Y);
}